// round 3
// baseline (speedup 1.0000x reference)
#include <cuda_runtime.h>

// CosinLoss fused: loss = mean_i( 1 - dot(pc_i,aug_i) / (max(||pc_i||,eps)*max(||aug_i||,eps)) )
// N=16384 rows, D=1024 fp32. HBM-streaming (128 MiB read).
// Layout: 512-thread CTA covers 2 rows (256 threads/row, 1 float4 per tensor per
// thread -> MLP_p1=2, low regs, high occupancy). Last-CTA-done final reduce.

#define CL_N   16384
#define CL_D   1024
#define CL_EPS 1e-12f
#define TPB    512
#define ROWS_PER_CTA 2
#define GRID   (CL_N / ROWS_PER_CTA)   // 8192

__device__ __align__(16) float g_part[GRID];
__device__ unsigned int g_count = 0;

__global__ __launch_bounds__(TPB)
void cos_loss_fused(const float* __restrict__ pc, const float* __restrict__ aug,
                    float* __restrict__ out) {
    const int t    = threadIdx.x;
    const int wid  = t >> 5;          // 0..15
    const int lane = t & 31;
    const int rsub = t >> 8;          // 0 or 1: which row in this CTA
    const int rt   = t & 255;         // thread index within row
    const int row  = blockIdx.x * ROWS_PER_CTA + rsub;

    const float4* __restrict__ p4 = reinterpret_cast<const float4*>(pc  + (size_t)row * CL_D);
    const float4* __restrict__ a4 = reinterpret_cast<const float4*>(aug + (size_t)row * CL_D);

    float4 p = p4[rt];
    float4 a = a4[rt];

    float dot = p.x * a.x + p.y * a.y + p.z * a.z + p.w * a.w;
    float npp = p.x * p.x + p.y * p.y + p.z * p.z + p.w * p.w;
    float naa = a.x * a.x + a.y * a.y + a.z * a.z + a.w * a.w;

    // Warp reduce (3 values)
    #pragma unroll
    for (int off = 16; off > 0; off >>= 1) {
        dot += __shfl_down_sync(0xFFFFFFFFu, dot, off);
        npp += __shfl_down_sync(0xFFFFFFFFu, npp, off);
        naa += __shfl_down_sync(0xFFFFFFFFu, naa, off);
    }

    __shared__ float s_dot[16], s_npp[16], s_naa[16];
    __shared__ float s_loss[ROWS_PER_CTA];
    __shared__ int   s_last;
    if (lane == 0) {
        s_dot[wid] = dot;
        s_npp[wid] = npp;
        s_naa[wid] = naa;
    }
    __syncthreads();

    // Warp 0 finishes row 0 (partials 0..7), warp 8 finishes row 1 (8..15).
    if ((wid == 0 || wid == 8) && lane < 8) {
        const int base = wid;          // 0 or 8
        dot = s_dot[base + lane];
        npp = s_npp[base + lane];
        naa = s_naa[base + lane];
        #pragma unroll
        for (int off = 4; off > 0; off >>= 1) {
            dot += __shfl_down_sync(0x000000FFu, dot, off);
            npp += __shfl_down_sync(0x000000FFu, npp, off);
            naa += __shfl_down_sync(0x000000FFu, naa, off);
        }
        if (lane == 0) {
            float np_ = fmaxf(sqrtf(npp), CL_EPS);
            float na_ = fmaxf(sqrtf(naa), CL_EPS);
            s_loss[wid >> 3] = 1.0f - dot / (np_ * na_);
        }
    }
    __syncthreads();

    if (t == 0) {
        g_part[blockIdx.x] = s_loss[0] + s_loss[1];
        __threadfence();
        unsigned int prev = atomicInc(&g_count, GRID - 1); // wraps to 0 on last
        s_last = (prev == GRID - 1);
    }
    __syncthreads();

    if (s_last) {
        __threadfence();  // acquire side: pair with writers' release fences
        // Reduce 8192 partials: 512 threads x 4 float4 (fixed order -> deterministic).
        const float4* __restrict__ v4 = reinterpret_cast<const float4*>(g_part);
        float s = 0.0f;
        #pragma unroll
        for (int i = 0; i < GRID / (TPB * 4); i++) {   // 4 iterations
            float4 v = v4[t + i * TPB];
            s += (v.x + v.y) + (v.z + v.w);
        }

        #pragma unroll
        for (int off = 16; off > 0; off >>= 1)
            s += __shfl_down_sync(0xFFFFFFFFu, s, off);

        __shared__ float s_sum[16];
        if (lane == 0) s_sum[wid] = s;
        __syncthreads();

        if (wid == 0) {
            s = (lane < 16) ? s_sum[lane] : 0.0f;
            #pragma unroll
            for (int off = 8; off > 0; off >>= 1)
                s += __shfl_down_sync(0xFFFFFFFFu, s, off);
            if (lane == 0)
                out[0] = s * (1.0f / (float)CL_N);
        }
    }
}

extern "C" void kernel_launch(void* const* d_in, const int* in_sizes, int n_in,
                              void* d_out, int out_size) {
    const float* pc  = (const float*)d_in[0];
    const float* aug = (const float*)d_in[1];
    float* out = (float*)d_out;

    cos_loss_fused<<<GRID, TPB>>>(pc, aug, out);
}

// round 4
// speedup vs baseline: 1.1803x; 1.1803x over previous
#include <cuda_runtime.h>

// CosinLoss fused persistent: loss = mean_i(1 - cos(pc_i, aug_i)), N=16384, D=1024 fp32.
// 1024 CTAs x 256 threads; each CTA loops 16 consecutive rows (1 float4/tensor/thread,
// MLP_p1=2, next-row prefetch across the reduce phase). Epilogue fence/atomic runs once
// per CTA (amortized over 256KB of loads). Last-CTA-done reduces 1024 partials.

#define CL_N   16384
#define CL_D   1024
#define CL_EPS 1e-12f
#define TPB    256
#define GRID   1024
#define ROWS_PER_CTA (CL_N / GRID)   // 16
#define F4_PER_ROW   (CL_D / 4)      // 256

__device__ __align__(16) float g_part[GRID];
__device__ unsigned int g_count = 0;

__global__ __launch_bounds__(TPB)
void cos_loss_persist(const float* __restrict__ pc, const float* __restrict__ aug,
                      float* __restrict__ out) {
    const int t    = threadIdx.x;
    const int wid  = t >> 5;      // 0..7
    const int lane = t & 31;

    const float4* __restrict__ p4 = reinterpret_cast<const float4*>(pc);
    const float4* __restrict__ a4 = reinterpret_cast<const float4*>(aug);

    const size_t base = (size_t)blockIdx.x * ROWS_PER_CTA * F4_PER_ROW + t;

    __shared__ float s_dot[8], s_npp[8], s_naa[8];
    __shared__ int   s_last;

    float loss_acc = 0.0f;   // valid on thread 0 only

    // Preload row 0
    float4 p = p4[base];
    float4 a = a4[base];

    #pragma unroll
    for (int i = 0; i < ROWS_PER_CTA; i++) {
        // Prefetch next row before the reduce/barrier phase of this row.
        float4 pn, an;
        if (i < ROWS_PER_CTA - 1) {
            pn = p4[base + (size_t)(i + 1) * F4_PER_ROW];
            an = a4[base + (size_t)(i + 1) * F4_PER_ROW];
        }

        float dot = p.x * a.x + p.y * a.y + p.z * a.z + p.w * a.w;
        float npp = p.x * p.x + p.y * p.y + p.z * p.z + p.w * p.w;
        float naa = a.x * a.x + a.y * a.y + a.z * a.z + a.w * a.w;

        #pragma unroll
        for (int off = 16; off > 0; off >>= 1) {
            dot += __shfl_down_sync(0xFFFFFFFFu, dot, off);
            npp += __shfl_down_sync(0xFFFFFFFFu, npp, off);
            naa += __shfl_down_sync(0xFFFFFFFFu, naa, off);
        }
        if (lane == 0) {
            s_dot[wid] = dot;
            s_npp[wid] = npp;
            s_naa[wid] = naa;
        }
        __syncthreads();

        if (wid == 0 && lane < 8) {
            dot = s_dot[lane];
            npp = s_npp[lane];
            naa = s_naa[lane];
            #pragma unroll
            for (int off = 4; off > 0; off >>= 1) {
                dot += __shfl_down_sync(0x000000FFu, dot, off);
                npp += __shfl_down_sync(0x000000FFu, npp, off);
                naa += __shfl_down_sync(0x000000FFu, naa, off);
            }
            if (lane == 0) {
                float np_ = fmaxf(sqrtf(npp), CL_EPS);
                float na_ = fmaxf(sqrtf(naa), CL_EPS);
                loss_acc += 1.0f - dot / (np_ * na_);
            }
        }
        __syncthreads();   // protect s_* before next iteration's writes

        p = pn;
        a = an;
    }

    // Per-CTA partial, then elect the last CTA to finish.
    if (t == 0) {
        g_part[blockIdx.x] = loss_acc;
        __threadfence();
        unsigned int prev = atomicInc(&g_count, GRID - 1); // wraps to 0 on last
        s_last = (prev == GRID - 1);
    }
    __syncthreads();

    if (s_last) {
        __threadfence();  // acquire: pair with writers' release fences
        // 1024 partials, 256 threads: fixed-order strided sum -> deterministic.
        float s = g_part[t] + g_part[t + 256] + g_part[t + 512] + g_part[t + 768];

        #pragma unroll
        for (int off = 16; off > 0; off >>= 1)
            s += __shfl_down_sync(0xFFFFFFFFu, s, off);

        __shared__ float s_sum[8];
        if (lane == 0) s_sum[wid] = s;
        __syncthreads();

        if (wid == 0) {
            s = (lane < 8) ? s_sum[lane] : 0.0f;
            #pragma unroll
            for (int off = 4; off > 0; off >>= 1)
                s += __shfl_down_sync(0xFFFFFFFFu, s, off);
            if (lane == 0)
                out[0] = s * (1.0f / (float)CL_N);
        }
    }
}

extern "C" void kernel_launch(void* const* d_in, const int* in_sizes, int n_in,
                              void* d_out, int out_size) {
    const float* pc  = (const float*)d_in[0];
    const float* aug = (const float*)d_in[1];
    float* out = (float*)d_out;

    cos_loss_persist<<<GRID, TPB>>>(pc, aug, out);
}

// round 5
// speedup vs baseline: 1.5366x; 1.3019x over previous
#include <cuda_runtime.h>

// CosinLoss: loss = mean_i( 1 - dot(pc_i,aug_i)/(max(||pc_i||,eps)*max(||aug_i||,eps)) )
// N=16384 rows, D=1024 fp32. HBM streaming, 128 MiB read.
// K1: 2 rows per 256-thread CTA (128 thr/row, 2 float4 per tensor per thread, MLP_p1=4),
//     grid 8192, no fences/atomics. K2: 64-CTA mid reduce. K3: final 64->1.

#define CL_N   16384
#define CL_D   1024
#define CL_EPS 1e-12f

__device__ __align__(16) float g_row_loss[CL_N];
__device__ __align__(16) float g_mid[64];

// ---------------- Kernel 1: per-row cosine loss ----------------
__global__ __launch_bounds__(256)
void row_cos_kernel(const float* __restrict__ pc, const float* __restrict__ aug) {
    const int t    = threadIdx.x;
    const int wid  = t >> 5;        // 0..7 (warps 0-3 -> row 0, warps 4-7 -> row 1)
    const int lane = t & 31;
    const int rsub = t >> 7;        // 0 or 1
    const int ct   = t & 127;       // thread index within row
    const size_t row = (size_t)blockIdx.x * 2 + rsub;

    const float4* __restrict__ p4 = reinterpret_cast<const float4*>(pc  + row * CL_D);
    const float4* __restrict__ a4 = reinterpret_cast<const float4*>(aug + row * CL_D);

    // 4 outstanding LDG.128 per thread (streaming hint).
    float4 p0 = __ldcs(&p4[ct]);
    float4 p1 = __ldcs(&p4[ct + 128]);
    float4 a0 = __ldcs(&a4[ct]);
    float4 a1 = __ldcs(&a4[ct + 128]);

    float dot = p0.x*a0.x + p0.y*a0.y + p0.z*a0.z + p0.w*a0.w
              + p1.x*a1.x + p1.y*a1.y + p1.z*a1.z + p1.w*a1.w;
    float npp = p0.x*p0.x + p0.y*p0.y + p0.z*p0.z + p0.w*p0.w
              + p1.x*p1.x + p1.y*p1.y + p1.z*p1.z + p1.w*p1.w;
    float naa = a0.x*a0.x + a0.y*a0.y + a0.z*a0.z + a0.w*a0.w
              + a1.x*a1.x + a1.y*a1.y + a1.z*a1.z + a1.w*a1.w;

    #pragma unroll
    for (int off = 16; off > 0; off >>= 1) {
        dot += __shfl_down_sync(0xFFFFFFFFu, dot, off);
        npp += __shfl_down_sync(0xFFFFFFFFu, npp, off);
        naa += __shfl_down_sync(0xFFFFFFFFu, naa, off);
    }

    __shared__ float s_dot[8], s_npp[8], s_naa[8];
    if (lane == 0) {
        s_dot[wid] = dot;
        s_npp[wid] = npp;
        s_naa[wid] = naa;
    }
    __syncthreads();

    // Warp 0 finalizes row 0 (slots 0..3); warp 4 finalizes row 1 (slots 4..7).
    if ((wid == 0 || wid == 4) && lane < 4) {
        const int base = wid;      // 0 or 4
        dot = s_dot[base + lane];
        npp = s_npp[base + lane];
        naa = s_naa[base + lane];
        #pragma unroll
        for (int off = 2; off > 0; off >>= 1) {
            dot += __shfl_down_sync(0x0000000Fu, dot, off);
            npp += __shfl_down_sync(0x0000000Fu, npp, off);
            naa += __shfl_down_sync(0x0000000Fu, naa, off);
        }
        if (lane == 0) {
            float np_ = fmaxf(sqrtf(npp), CL_EPS);
            float na_ = fmaxf(sqrtf(naa), CL_EPS);
            g_row_loss[(size_t)blockIdx.x * 2 + (wid >> 2)] = 1.0f - dot / (np_ * na_);
        }
    }
}

// ---------------- Kernel 2: 16384 -> 64 partials ----------------
__global__ __launch_bounds__(256)
void mid_reduce_kernel() {
    const int t    = threadIdx.x;
    const int wid  = t >> 5;
    const int lane = t & 31;

    float s = g_row_loss[blockIdx.x * 256 + t];

    #pragma unroll
    for (int off = 16; off > 0; off >>= 1)
        s += __shfl_down_sync(0xFFFFFFFFu, s, off);

    __shared__ float s_sum[8];
    if (lane == 0) s_sum[wid] = s;
    __syncthreads();

    if (wid == 0) {
        s = (lane < 8) ? s_sum[lane] : 0.0f;
        #pragma unroll
        for (int off = 4; off > 0; off >>= 1)
            s += __shfl_down_sync(0xFFFFFFFFu, s, off);
        if (lane == 0) g_mid[blockIdx.x] = s;
    }
}

// ---------------- Kernel 3: 64 -> mean ----------------
__global__ __launch_bounds__(64)
void final_reduce_kernel(float* __restrict__ out) {
    const int t    = threadIdx.x;
    const int wid  = t >> 5;
    const int lane = t & 31;

    float s = g_mid[t];

    #pragma unroll
    for (int off = 16; off > 0; off >>= 1)
        s += __shfl_down_sync(0xFFFFFFFFu, s, off);

    __shared__ float s_sum[2];
    if (lane == 0) s_sum[wid] = s;
    __syncthreads();

    if (t == 0)
        out[0] = (s_sum[0] + s_sum[1]) * (1.0f / (float)CL_N);
}

extern "C" void kernel_launch(void* const* d_in, const int* in_sizes, int n_in,
                              void* d_out, int out_size) {
    const float* pc  = (const float*)d_in[0];
    const float* aug = (const float*)d_in[1];
    float* out = (float*)d_out;

    row_cos_kernel<<<CL_N / 2, 256>>>(pc, aug);
    mid_reduce_kernel<<<64, 256>>>();
    final_reduce_kernel<<<1, 64>>>(out);
}

// round 6
// speedup vs baseline: 1.5642x; 1.0180x over previous
#include <cuda_runtime.h>

// CosinLoss: loss = mean_i( 1 - dot(pc_i,aug_i)/(max(||pc_i||,eps)*max(||aug_i||,eps)) )
// N=16384 rows, D=1024 fp32. HBM streaming, 128 MiB read.
// K1: 4 rows per 256-thread CTA (64 thr/row, 4 float4/tensor/thread -> MLP_p1=8),
//     grid 4096, emits per-CTA sum of 4 row losses (no fences/atomics).
// K2: single CTA (1024 thr) reduces 4096 partials -> mean.

#define CL_N   16384
#define CL_D   1024
#define CL_EPS 1e-12f
#define GRID1  4096

__device__ __align__(16) float g_part[GRID1];

// ---------------- Kernel 1: 4 rows/CTA cosine loss, per-CTA sum ----------------
__global__ __launch_bounds__(256)
void row_cos_kernel(const float* __restrict__ pc, const float* __restrict__ aug) {
    const int t    = threadIdx.x;
    const int wid  = t >> 5;        // 0..7; warps 2r,2r+1 own row r
    const int lane = t & 31;
    const int rsub = t >> 6;        // 0..3: row within CTA
    const int ct   = t & 63;        // thread index within row (64 thr/row)
    const size_t row = (size_t)blockIdx.x * 4 + rsub;

    const float4* __restrict__ p4 = reinterpret_cast<const float4*>(pc  + row * CL_D);
    const float4* __restrict__ a4 = reinterpret_cast<const float4*>(aug + row * CL_D);

    // 8 outstanding LDG.128 per thread, streaming hint.
    float4 p0 = __ldcs(&p4[ct      ]);
    float4 p1 = __ldcs(&p4[ct +  64]);
    float4 p2 = __ldcs(&p4[ct + 128]);
    float4 p3 = __ldcs(&p4[ct + 192]);
    float4 a0 = __ldcs(&a4[ct      ]);
    float4 a1 = __ldcs(&a4[ct +  64]);
    float4 a2 = __ldcs(&a4[ct + 128]);
    float4 a3 = __ldcs(&a4[ct + 192]);

    float dot = p0.x*a0.x + p0.y*a0.y + p0.z*a0.z + p0.w*a0.w
              + p1.x*a1.x + p1.y*a1.y + p1.z*a1.z + p1.w*a1.w
              + p2.x*a2.x + p2.y*a2.y + p2.z*a2.z + p2.w*a2.w
              + p3.x*a3.x + p3.y*a3.y + p3.z*a3.z + p3.w*a3.w;
    float npp = p0.x*p0.x + p0.y*p0.y + p0.z*p0.z + p0.w*p0.w
              + p1.x*p1.x + p1.y*p1.y + p1.z*p1.z + p1.w*p1.w
              + p2.x*p2.x + p2.y*p2.y + p2.z*p2.z + p2.w*p2.w
              + p3.x*p3.x + p3.y*p3.y + p3.z*p3.z + p3.w*p3.w;
    float naa = a0.x*a0.x + a0.y*a0.y + a0.z*a0.z + a0.w*a0.w
              + a1.x*a1.x + a1.y*a1.y + a1.z*a1.z + a1.w*a1.w
              + a2.x*a2.x + a2.y*a2.y + a2.z*a2.z + a2.w*a2.w
              + a3.x*a3.x + a3.y*a3.y + a3.z*a3.z + a3.w*a3.w;

    #pragma unroll
    for (int off = 16; off > 0; off >>= 1) {
        dot += __shfl_down_sync(0xFFFFFFFFu, dot, off);
        npp += __shfl_down_sync(0xFFFFFFFFu, npp, off);
        naa += __shfl_down_sync(0xFFFFFFFFu, naa, off);
    }

    __shared__ float s_dot[8], s_npp[8], s_naa[8];
    if (lane == 0) {
        s_dot[wid] = dot;
        s_npp[wid] = npp;
        s_naa[wid] = naa;
    }
    __syncthreads();

    // Warp 0, lanes 0..7: slot pairs (2r, 2r+1) belong to row r.
    if (wid == 0 && lane < 8) {
        dot = s_dot[lane];
        npp = s_npp[lane];
        naa = s_naa[lane];
        // combine the two warp-halves of each row
        dot += __shfl_xor_sync(0x000000FFu, dot, 1);
        npp += __shfl_xor_sync(0x000000FFu, npp, 1);
        naa += __shfl_xor_sync(0x000000FFu, naa, 1);

        float loss = 0.0f;
        if ((lane & 1) == 0) {
            float np_ = fmaxf(sqrtf(npp), CL_EPS);
            float na_ = fmaxf(sqrtf(naa), CL_EPS);
            loss = 1.0f - dot / (np_ * na_);
        }
        // sum the 4 row losses (held on even lanes) -> lane 0
        loss += __shfl_down_sync(0x000000FFu, loss, 4);
        loss += __shfl_down_sync(0x000000FFu, loss, 2);
        if (lane == 0)
            g_part[blockIdx.x] = loss;   // odd-lane contributions are 0
    }
}

// ---------------- Kernel 2: 4096 partials -> mean ----------------
__global__ __launch_bounds__(1024)
void final_reduce_kernel(float* __restrict__ out) {
    const int t    = threadIdx.x;
    const int wid  = t >> 5;
    const int lane = t & 31;

    const float4* __restrict__ v4 = reinterpret_cast<const float4*>(g_part);
    float4 v = v4[t];                  // 1024 threads x 1 float4 = 4096 floats
    float s = (v.x + v.y) + (v.z + v.w);

    #pragma unroll
    for (int off = 16; off > 0; off >>= 1)
        s += __shfl_down_sync(0xFFFFFFFFu, s, off);

    __shared__ float s_sum[32];
    if (lane == 0) s_sum[wid] = s;
    __syncthreads();

    if (wid == 0) {
        s = s_sum[lane];
        #pragma unroll
        for (int off = 16; off > 0; off >>= 1)
            s += __shfl_down_sync(0xFFFFFFFFu, s, off);
        if (lane == 0)
            out[0] = s * (1.0f / (float)CL_N);
    }
}

extern "C" void kernel_launch(void* const* d_in, const int* in_sizes, int n_in,
                              void* d_out, int out_size) {
    const float* pc  = (const float*)d_in[0];
    const float* aug = (const float*)d_in[1];
    float* out = (float*)d_out;

    row_cos_kernel<<<GRID1, 256>>>(pc, aug);
    final_reduce_kernel<<<1, 1024>>>(out);
}